// round 1
// baseline (speedup 1.0000x reference)
#include <cuda_runtime.h>
#include <cuda_bf16.h>
#include <math.h>

// Problem constants (fixed by the dataset)
#define NS 100000
#define NE 100000
#define EDG 1600000
#define D 256
#define H 8
#define HD 32
#define FEAT 64
#define DFF 512

// ---------------- device scratch (no allocations allowed) ----------------
__device__ float g_z[(size_t)NE * D];     // e-node per-head projections [NE, 256]
__device__ float g_df[(size_t)NS * D];    // dst-feat projections       [NS, 256]
__device__ float g_h[(size_t)NS * D];     // attention output (post-ELU)[NS, 256]
__device__ float g_x[(size_t)NS * D];     // proj output (residual src) [NS, 256]
__device__ float g_xn[(size_t)NS * D];    // layernorm output           [NS, 256]
__device__ float g_t[(size_t)NS * DFF];   // ffn hidden                 [NS, 512]
__device__ float g_Wz[D * D];             // repacked fc_w      [256,256]
__device__ float g_Wd[FEAT * D];          // repacked dstfeat_w [64,256]
__device__ int   g_counts[NS];
__device__ int   g_offsets[NS + 1];
__device__ int   g_cursor[NS];
__device__ int   g_csr_src[EDG];

// ---------------- small helpers ----------------
__device__ __forceinline__ float gelu_tanh(float x) {
    const float c = 0.7978845608028654f;
    float x3 = x * x * x;
    float t = tanhf(c * (x + 0.044715f * x3));
    return 0.5f * x * (1.0f + t);
}

// ---------------- weight repack: (H, K, HD) -> [K, H*HD] ----------------
__global__ void repack_w(const float* __restrict__ w, float* __restrict__ out, int K) {
    int idx = blockIdx.x * blockDim.x + threadIdx.x;
    if (idx >= K * 256) return;
    int k = idx >> 8;
    int n = idx & 255;
    out[idx] = w[(n >> 5) * (K * 32) + k * 32 + (n & 31)];
}

// ---------------- generic fp32 SGEMM: C = act(A @ B + bias) + res ----------------
// A is split: rows read from A0 for k < ksplit, from A1 for k >= ksplit.
// A row-major [M,K(lda)], B row-major [K,N]. Block 128x128, thread tile 8x8, K-tile 8.
template <int ACT, bool HAS_BIAS, bool HAS_RES>
__global__ void __launch_bounds__(256) sgemm_k(
    const float* __restrict__ A0, int lda0,
    const float* __restrict__ A1, int lda1, int ksplit,
    const float* __restrict__ B,
    const float* __restrict__ bias,
    const float* __restrict__ res, int ldr,
    float* __restrict__ C,
    int M, int N, int K)
{
    __shared__ float As[8][132];
    __shared__ float Bs[8][128];

    int t  = threadIdx.x;
    int m0 = blockIdx.y * 128;
    int n0 = blockIdx.x * 128;
    int tx = t & 15;
    int ty = t >> 4;

    int a_m = t >> 1;
    int a_k = (t & 1) * 4;
    int b_k = t >> 5;
    int b_n = (t & 31) * 4;

    float acc[8][8];
#pragma unroll
    for (int i = 0; i < 8; i++)
#pragma unroll
        for (int j = 0; j < 8; j++) acc[i][j] = 0.0f;

    for (int k0 = 0; k0 < K; k0 += 8) {
        // load A tile (guard M), transposed into As[k][m]
        int gm = m0 + a_m;
        float4 av = make_float4(0.f, 0.f, 0.f, 0.f);
        if (gm < M) {
            int kk = k0 + a_k;
            const float* p = (kk < ksplit)
                                 ? (A0 + (size_t)gm * lda0 + kk)
                                 : (A1 + (size_t)gm * lda1 + (kk - ksplit));
            av = *(const float4*)p;
        }
        As[a_k + 0][a_m] = av.x;
        As[a_k + 1][a_m] = av.y;
        As[a_k + 2][a_m] = av.z;
        As[a_k + 3][a_m] = av.w;

        // load B tile (N is a multiple of 128 in all our calls)
        float4 bv = *(const float4*)(B + (size_t)(k0 + b_k) * N + n0 + b_n);
        *(float4*)&Bs[b_k][b_n] = bv;

        __syncthreads();

#pragma unroll
        for (int kk = 0; kk < 8; kk++) {
            float a[8], b[8];
            *(float4*)(a)     = *(const float4*)&As[kk][ty * 8];
            *(float4*)(a + 4) = *(const float4*)&As[kk][ty * 8 + 4];
            *(float4*)(b)     = *(const float4*)&Bs[kk][tx * 8];
            *(float4*)(b + 4) = *(const float4*)&Bs[kk][tx * 8 + 4];
#pragma unroll
            for (int i = 0; i < 8; i++)
#pragma unroll
                for (int j = 0; j < 8; j++) acc[i][j] += a[i] * b[j];
        }
        __syncthreads();
    }

    // epilogue
#pragma unroll
    for (int i = 0; i < 8; i++) {
        int m = m0 + ty * 8 + i;
        if (m >= M) continue;
#pragma unroll
        for (int jv = 0; jv < 2; jv++) {
            int n = n0 + tx * 8 + jv * 4;
            float4 v;
            float* vp = &v.x;
#pragma unroll
            for (int j = 0; j < 4; j++) {
                float val = acc[i][jv * 4 + j];
                if (HAS_BIAS) val += bias[n + j];
                if (ACT == 1) val = gelu_tanh(val);
                vp[j] = val;
            }
            if (HAS_RES) {
                float4 r = *(const float4*)(res + (size_t)m * ldr + n);
                v.x += r.x; v.y += r.y; v.z += r.z; v.w += r.w;
            }
            *(float4*)(C + (size_t)m * N + n) = v;
        }
    }
}

// ---------------- CSR build ----------------
__global__ void zero_counts() {
    int i = blockIdx.x * blockDim.x + threadIdx.x;
    if (i < NS) g_counts[i] = 0;
}

__global__ void hist_kernel(const int* __restrict__ edge_dst) {
    int i = blockIdx.x * blockDim.x + threadIdx.x;
    if (i < EDG) atomicAdd(&g_counts[edge_dst[i]], 1);
}

__global__ void scan_kernel() {
    __shared__ int warp_sums[32];
    __shared__ int s_carry;
    int t = threadIdx.x;
    int lane = t & 31;
    int w = t >> 5;
    if (t == 0) { s_carry = 0; g_offsets[0] = 0; }
    __syncthreads();
    for (int base = 0; base < NS; base += 1024) {
        int i = base + t;
        int v = (i < NS) ? g_counts[i] : 0;
        int x = v;
#pragma unroll
        for (int o = 1; o < 32; o <<= 1) {
            int y = __shfl_up_sync(0xFFFFFFFFu, x, o);
            if (lane >= o) x += y;
        }
        if (lane == 31) warp_sums[w] = x;
        __syncthreads();
        if (w == 0) {
            int sv = warp_sums[lane];
#pragma unroll
            for (int o = 1; o < 32; o <<= 1) {
                int y = __shfl_up_sync(0xFFFFFFFFu, sv, o);
                if (lane >= o) sv += y;
            }
            warp_sums[lane] = sv;
        }
        __syncthreads();
        int incl = x + (w > 0 ? warp_sums[w - 1] : 0) + s_carry;
        if (i < NS) {
            g_offsets[i + 1] = incl;
            g_cursor[i] = incl - v;
        }
        __syncthreads();
        if (t == 1023) s_carry = incl;
        __syncthreads();
    }
}

__global__ void scatter_kernel(const int* __restrict__ edge_src,
                               const int* __restrict__ edge_dst) {
    int i = blockIdx.x * blockDim.x + threadIdx.x;
    if (i >= EDG) return;
    int dst = edge_dst[i];
    int pos = atomicAdd(&g_cursor[dst], 1);
    g_csr_src[pos] = edge_src[i];
}

// ---------------- attention: one warp per dst, online softmax ----------------
__global__ void attn_kernel() {
    int gwarp = (blockIdx.x * blockDim.x + threadIdx.x) >> 5;
    if (gwarp >= NS) return;
    int lane = threadIdx.x & 31;

    int beg = g_offsets[gwarp];
    int end = g_offsets[gwarp + 1];

    const float* dfp = g_df + (size_t)gwarp * 256;
    float dfr[8];
#pragma unroll
    for (int r = 0; r < 8; r++) dfr[r] = dfp[r * 32 + lane];

    float m[8], den[8], acc[8];
#pragma unroll
    for (int r = 0; r < 8; r++) { m[r] = -1e30f; den[r] = 0.0f; acc[r] = 0.0f; }

    for (int e = beg; e < end; e++) {
        int src = g_csr_src[e];
        const float* zp = g_z + (size_t)src * 256;
        float zr[8], s[8];
#pragma unroll
        for (int r = 0; r < 8; r++) {
            zr[r] = __ldg(zp + r * 32 + lane);
            s[r] = zr[r] * dfr[r];
        }
        // per-head warp reductions
#pragma unroll
        for (int r = 0; r < 8; r++) {
#pragma unroll
            for (int off = 16; off > 0; off >>= 1)
                s[r] += __shfl_xor_sync(0xFFFFFFFFu, s[r], off);
        }
        // online softmax update
#pragma unroll
        for (int r = 0; r < 8; r++) {
            float mn = fmaxf(m[r], s[r]);
            float scale = __expf(m[r] - mn);
            float wgt = __expf(s[r] - mn);
            den[r] = den[r] * scale + wgt;
            acc[r] = acc[r] * scale + wgt * zr[r];
            m[r] = mn;
        }
    }

    float* hp = g_h + (size_t)gwarp * 256;
#pragma unroll
    for (int r = 0; r < 8; r++) {
        float v = acc[r] / den[r];
        v = (v > 0.0f) ? v : expm1f(v);  // ELU(alpha=1)
        hp[r * 32 + lane] = v;
    }
}

// ---------------- layernorm: one warp per row ----------------
__global__ void ln_kernel(const float* __restrict__ x,
                          const float* __restrict__ gam,
                          const float* __restrict__ bet,
                          float* __restrict__ y) {
    int row = (blockIdx.x * blockDim.x + threadIdx.x) >> 5;
    if (row >= NS) return;
    int lane = threadIdx.x & 31;
    const float* xp = x + (size_t)row * 256;
    float v[8];
    float s = 0.0f, s2 = 0.0f;
#pragma unroll
    for (int r = 0; r < 8; r++) {
        v[r] = xp[r * 32 + lane];
        s += v[r];
        s2 += v[r] * v[r];
    }
#pragma unroll
    for (int off = 16; off > 0; off >>= 1) {
        s  += __shfl_xor_sync(0xFFFFFFFFu, s, off);
        s2 += __shfl_xor_sync(0xFFFFFFFFu, s2, off);
    }
    float mean = s * (1.0f / 256.0f);
    float var = s2 * (1.0f / 256.0f) - mean * mean;
    float inv = rsqrtf(var + 1e-6f);
    float* yp = y + (size_t)row * 256;
#pragma unroll
    for (int r = 0; r < 8; r++) {
        int c = r * 32 + lane;
        yp[c] = (v[r] - mean) * inv * gam[c] + bet[c];
    }
}

// ---------------- launch ----------------
extern "C" void kernel_launch(void* const* d_in, const int* in_sizes, int n_in,
                              void* d_out, int out_size) {
    const float* s_in      = (const float*)d_in[0];
    const float* e_in      = (const float*)d_in[1];
    const float* dst_feat  = (const float*)d_in[2];
    const float* fc_w      = (const float*)d_in[3];
    const float* dstfeat_w = (const float*)d_in[4];
    const float* proj_w    = (const float*)d_in[5];
    const float* proj_b    = (const float*)d_in[6];
    const float* ln_g      = (const float*)d_in[7];
    const float* ln_b      = (const float*)d_in[8];
    const float* w1        = (const float*)d_in[9];
    const float* b1        = (const float*)d_in[10];
    const float* w2        = (const float*)d_in[11];
    const float* b2        = (const float*)d_in[12];
    const int*   edge_src  = (const int*)d_in[13];
    const int*   edge_dst  = (const int*)d_in[14];
    float* out = (float*)d_out;

    float *zp, *dfp, *hp, *xp, *xnp, *tp, *wzp, *wdp;
    cudaGetSymbolAddress((void**)&zp,  g_z);
    cudaGetSymbolAddress((void**)&dfp, g_df);
    cudaGetSymbolAddress((void**)&hp,  g_h);
    cudaGetSymbolAddress((void**)&xp,  g_x);
    cudaGetSymbolAddress((void**)&xnp, g_xn);
    cudaGetSymbolAddress((void**)&tp,  g_t);
    cudaGetSymbolAddress((void**)&wzp, g_Wz);
    cudaGetSymbolAddress((void**)&wdp, g_Wd);

    const int TB = 256;
    dim3 gB(2, (NS + 127) / 128);

    // 1) repack per-head weights into plain [K, 256] matrices
    repack_w<<<(D * 256 + TB - 1) / TB, TB>>>(fc_w, wzp, D);
    repack_w<<<(FEAT * 256 + TB - 1) / TB, TB>>>(dstfeat_w, wdp, FEAT);

    // 2) z = e @ Wz  [NE,256]
    sgemm_k<0, false, false><<<dim3(2, (NE + 127) / 128), TB>>>(
        e_in, D, e_in, D, D, wzp, nullptr, nullptr, 0, zp, NE, 256, D);

    // 3) df = dst_feat @ Wd  [NS,256]
    sgemm_k<0, false, false><<<gB, TB>>>(
        dst_feat, FEAT, dst_feat, FEAT, FEAT, wdp, nullptr, nullptr, 0, dfp, NS, 256, FEAT);

    // 4) CSR build by dst
    zero_counts<<<(NS + TB - 1) / TB, TB>>>();
    hist_kernel<<<(EDG + TB - 1) / TB, TB>>>(edge_dst);
    scan_kernel<<<1, 1024>>>();
    scatter_kernel<<<(EDG + TB - 1) / TB, TB>>>(edge_src, edge_dst);

    // 5) attention + ELU -> g_h
    attn_kernel<<<(NS * 32 + TB - 1) / TB, TB>>>();

    // 6) proj: [h | s] @ proj_w + b -> g_x
    sgemm_k<0, true, false><<<gB, TB>>>(
        hp, 256, s_in, 256, 256, proj_w, proj_b, nullptr, 0, xp, NS, 256, 512);

    // 7) layernorm -> g_xn
    ln_kernel<<<(NS * 32 + TB - 1) / TB, TB>>>(xp, ln_g, ln_b, xnp);

    // 8) ffn1: gelu(xn @ w1 + b1) -> g_t
    sgemm_k<1, true, false><<<dim3(4, (NS + 127) / 128), TB>>>(
        xnp, 256, xnp, 256, 256, w1, b1, nullptr, 0, tp, NS, DFF, 256);

    // 9) ffn2: g_t @ w2 + b2 + g_x -> out
    sgemm_k<0, true, true><<<gB, TB>>>(
        tp, DFF, tp, DFF, DFF, w2, b2, xp, 256, out, NS, 256, DFF);
}